// round 11
// baseline (speedup 1.0000x reference)
#include <cuda_runtime.h>
#include <cuda_bf16.h>
#include <cuda_fp16.h>
#include <cstdint>

#define Bn  16
#define Qn  64
#define Kn  1024
#define Dn  256
#define Hn  128
#define DVn 256

// Scratch (device globals; no allocation allowed in kernel_launch)
__device__ float g_kproj[Bn * Kn * Hn];        // 8 MB
__device__ float g_qproj[Bn * Qn * Hn];        // 0.5 MB
__device__ float g_scores[Bn * Qn * Kn];       // 4 MB (scores, then attn)
__device__ float g_part[16][Bn][Qn][DVn];      // 16 MB AV partials (zero-init;
                                               // chunks beyond vlen are never
                                               // written and stay exactly 0)

// ---------------------------------------------------------------------------
// mma.sync m16n8k16 (row.col) fp32 accum, bf16 and f16 flavors; ldmatrix.
// All compute_80+ PTX (the harness's compute_100 virtual target rejects
// tcgen05; these pass).
// ---------------------------------------------------------------------------
__device__ __forceinline__ void mma16816(float* d, const uint32_t* a,
                                         const uint32_t* b) {
    asm volatile(
        "mma.sync.aligned.m16n8k16.row.col.f32.bf16.bf16.f32 "
        "{%0,%1,%2,%3}, {%4,%5,%6,%7}, {%8,%9}, {%0,%1,%2,%3};"
        : "+f"(d[0]), "+f"(d[1]), "+f"(d[2]), "+f"(d[3])
        : "r"(a[0]), "r"(a[1]), "r"(a[2]), "r"(a[3]), "r"(b[0]), "r"(b[1]));
}

__device__ __forceinline__ void mma16816h(float* d, const uint32_t* a,
                                          const uint32_t* b) {
    asm volatile(
        "mma.sync.aligned.m16n8k16.row.col.f32.f16.f16.f32 "
        "{%0,%1,%2,%3}, {%4,%5,%6,%7}, {%8,%9}, {%0,%1,%2,%3};"
        : "+f"(d[0]), "+f"(d[1]), "+f"(d[2]), "+f"(d[3])
        : "r"(a[0]), "r"(a[1]), "r"(a[2]), "r"(a[3]), "r"(b[0]), "r"(b[1]));
}

// A fragment (16x16, row-major source): r0..r3 = a0..a3.
__device__ __forceinline__ void ldm_x4(uint32_t* r, const __nv_bfloat16* p) {
    uint32_t a = (uint32_t)__cvta_generic_to_shared(p);
    asm volatile(
        "ldmatrix.sync.aligned.m8n8.x4.shared.b16 {%0,%1,%2,%3}, [%4];"
        : "=r"(r[0]), "=r"(r[1]), "=r"(r[2]), "=r"(r[3]) : "r"(a));
}
// B fragments for TWO adjacent n-tiles from [k][n]-layout source (transposed
// in-flight): {r0,r1} = n-tile j, {r2,r3} = n-tile j+1.
__device__ __forceinline__ void ldm_x4t(uint32_t* r, const __nv_bfloat16* p) {
    uint32_t a = (uint32_t)__cvta_generic_to_shared(p);
    asm volatile(
        "ldmatrix.sync.aligned.m8n8.x4.trans.shared.b16 {%0,%1,%2,%3}, [%4];"
        : "=r"(r[0]), "=r"(r[1]), "=r"(r[2]), "=r"(r[3]) : "r"(a));
}

__device__ __forceinline__ __nv_bfloat162 hi2(float a, float b) {
    return __halves2bfloat162(__float2bfloat16(a), __float2bfloat16(b));
}
__device__ __forceinline__ __nv_bfloat162 lo2(float a, float b) {
    return __halves2bfloat162(
        __float2bfloat16(a - __bfloat162float(__float2bfloat16(a))),
        __float2bfloat16(b - __bfloat162float(__float2bfloat16(b))));
}

// pack two fp32 -> f16x2 (F2FP, full-rate alu class) then tanh.approx.f16x2
// (one MUFU op per 2 elements). No scalar F2F unpacks anywhere (R9's mistake).
__device__ __forceinline__ uint32_t tanh2(float hi, float lo) {
    uint32_t p, t;
    asm("cvt.rn.f16x2.f32 %0, %1, %2;" : "=r"(p) : "f"(hi), "f"(lo));
    asm("tanh.approx.f16x2 %0, %1;" : "=r"(t) : "r"(p));
    return t;
}

#define KC 32
#define APAD 40   // A tiles [m][32+8]: ldmatrix phases conflict-free
#define WPAD 136  // W tile [32][128+8]: row stride 68 words mod 32 = 4
#define VPAD 264  // V tile [32][256+8]: row stride 132 words mod 32 = 4

// ---------------------------------------------------------------------------
// Projection P[r, h] = sum_d X[r, d] * W[d, h] via HMMA, split-bf16 3-product
// (unchanged from R10: natural-layout staging + ldmatrix + prefetch).
// ---------------------------------------------------------------------------
__global__ void __launch_bounds__(256, 1) proj_mma_kernel(
    const float* __restrict__ keys, const float* __restrict__ queries,
    const float* __restrict__ Wk, const float* __restrict__ Wq) {
    __shared__ __align__(16) __nv_bfloat16 sAh[128][APAD];
    __shared__ __align__(16) __nv_bfloat16 sAl[128][APAD];
    __shared__ __align__(16) __nv_bfloat16 sWh[32][WPAD];  // [d][h] natural
    __shared__ __align__(16) __nv_bfloat16 sWl[32][WPAD];

    const int tid  = threadIdx.x;
    const int wid  = tid >> 5;
    const int lane = tid & 31;
    const int cid  = blockIdx.x;

    const float* X;
    const float* W;
    float* P;
    int row0;
    if (cid < 128) {
        X = keys; W = Wk; P = g_kproj; row0 = cid * 128;
    } else {
        X = queries; W = Wq; P = g_qproj; row0 = (cid - 128) * 128;
    }

    const int wm   = (wid & 1) * 64;
    const int wn   = (wid >> 1) * 32;
    const int gid  = lane >> 2;
    const int tig  = lane & 3;
    const int lrow = lane & 15;
    const int lcol = (lane >> 4) * 8;

    float acc[4][4][4];
#pragma unroll
    for (int im = 0; im < 4; im++)
#pragma unroll
        for (int j = 0; j < 4; j++)
#pragma unroll
            for (int r = 0; r < 4; r++) acc[im][j][r] = 0.f;

    float4 xPre[4], wPre[4];
#pragma unroll
    for (int i = 0; i < 4; i++) {
        int idx = tid + i * 256;
        int r = idx >> 3, kq = idx & 7;
        xPre[i] = *(const float4*)&X[(size_t)(row0 + r) * Dn + kq * 4];
    }
#pragma unroll
    for (int i = 0; i < 4; i++) {
        int idx = tid + i * 256;
        int k = idx >> 5, n4 = idx & 31;
        wPre[i] = *(const float4*)&W[(size_t)k * Hn + n4 * 4];
    }

    for (int kc = 0; kc < Dn; kc += KC) {
#pragma unroll
        for (int i = 0; i < 4; i++) {
            int idx = tid + i * 256;
            int r = idx >> 3, kq = idx & 7;
            float4 v = xPre[i];
            *(__nv_bfloat162*)&sAh[r][kq * 4]     = hi2(v.x, v.y);
            *(__nv_bfloat162*)&sAh[r][kq * 4 + 2] = hi2(v.z, v.w);
            *(__nv_bfloat162*)&sAl[r][kq * 4]     = lo2(v.x, v.y);
            *(__nv_bfloat162*)&sAl[r][kq * 4 + 2] = lo2(v.z, v.w);
        }
#pragma unroll
        for (int i = 0; i < 4; i++) {
            int idx = tid + i * 256;
            int k = idx >> 5, n4 = idx & 31;
            float4 v = wPre[i];
            *(__nv_bfloat162*)&sWh[k][n4 * 4]     = hi2(v.x, v.y);
            *(__nv_bfloat162*)&sWh[k][n4 * 4 + 2] = hi2(v.z, v.w);
            *(__nv_bfloat162*)&sWl[k][n4 * 4]     = lo2(v.x, v.y);
            *(__nv_bfloat162*)&sWl[k][n4 * 4 + 2] = lo2(v.z, v.w);
        }
        __syncthreads();

        if (kc + KC < Dn) {
#pragma unroll
            for (int i = 0; i < 4; i++) {
                int idx = tid + i * 256;
                int r = idx >> 3, kq = idx & 7;
                xPre[i] = *(const float4*)
                    &X[(size_t)(row0 + r) * Dn + kc + KC + kq * 4];
            }
#pragma unroll
            for (int i = 0; i < 4; i++) {
                int idx = tid + i * 256;
                int k = idx >> 5, n4 = idx & 31;
                wPre[i] = *(const float4*)
                    &W[(size_t)(kc + KC + k) * Hn + n4 * 4];
            }
        }

#pragma unroll
        for (int s = 0; s < 2; s++) {
            uint32_t Ah[4][4], Al[4][4];
#pragma unroll
            for (int im = 0; im < 4; im++) {
                ldm_x4(Ah[im], &sAh[wm + im * 16 + lrow][s * 16 + lcol]);
                ldm_x4(Al[im], &sAl[wm + im * 16 + lrow][s * 16 + lcol]);
            }
            uint32_t Bh[4][2], Bl[4][2];
#pragma unroll
            for (int jj = 0; jj < 2; jj++) {
                uint32_t t[4];
                ldm_x4t(t, &sWh[s * 16 + lrow][wn + jj * 16 + lcol]);
                Bh[jj * 2][0] = t[0]; Bh[jj * 2][1] = t[1];
                Bh[jj * 2 + 1][0] = t[2]; Bh[jj * 2 + 1][1] = t[3];
                ldm_x4t(t, &sWl[s * 16 + lrow][wn + jj * 16 + lcol]);
                Bl[jj * 2][0] = t[0]; Bl[jj * 2][1] = t[1];
                Bl[jj * 2 + 1][0] = t[2]; Bl[jj * 2 + 1][1] = t[3];
            }
#pragma unroll
            for (int im = 0; im < 4; im++) {
#pragma unroll
                for (int j = 0; j < 4; j++) {
                    mma16816(acc[im][j], Ah[im], Bh[j]);
                    mma16816(acc[im][j], Al[im], Bh[j]);
                    mma16816(acc[im][j], Ah[im], Bl[j]);
                }
            }
        }
        __syncthreads();
    }

#pragma unroll
    for (int im = 0; im < 4; im++) {
        int r_lo = row0 + wm + im * 16 + gid;
#pragma unroll
        for (int j = 0; j < 4; j++) {
            int c = wn + j * 8 + tig * 2;
            *(float2*)&P[(size_t)r_lo * Hn + c] =
                make_float2(acc[im][j][0], acc[im][j][1]);
            *(float2*)&P[(size_t)(r_lo + 8) * Hn + c] =
                make_float2(acc[im][j][2], acc[im][j][3]);
        }
    }
}

// ---------------------------------------------------------------------------
// scores[b, q, k] = sum_h wv[h] * tanh(qproj[b,q,h] + kproj[b,k,h])
// R11: tanh.approx.f16x2 (halves the MUFU count: 30us floor -> 15us) feeding
// mma.m16n8k16.f32.f16.f16.f32 directly as A fragments, with B = wv
// replicated across the n dimension (only D column 0 used). fp32 adds, F2FP
// pack (full-rate), NO scalar F2F unpacks (R9's quarter-rate mistake), fp32
// accumulation inside the tensor core.
// CTA = (k-tile 32, q-half 32, b); warp-task = (one q, one 16-wide k-tile):
// thread (gid,tig) computes exactly its a0..a3 fragment elements.
// ---------------------------------------------------------------------------
__global__ void __launch_bounds__(256) scores_kernel(
    const float* __restrict__ wv) {
    const int b   = blockIdx.z;
    const int qh  = blockIdx.y * 32;
    const int k0  = blockIdx.x * 32;
    const int tid = threadIdx.x;

    __shared__ __align__(16) float sQ[32][Hn];    // 16 KB
    __shared__ __align__(16) float sK[32][132];   // 16.9 KB (compute reads
                                                  // conflict-free: bank =
                                                  // (4*gid + 2*tig) mod 32)
    __shared__ __align__(4) __half sWvH[Hn];

    {
        const float4* src =
            (const float4*)(g_qproj + ((size_t)b * Qn + qh) * Hn);
        float4* dst = (float4*)&sQ[0][0];
#pragma unroll
        for (int i = 0; i < 4; i++) {
            int j = tid + i * 256;
            dst[j] = src[j];
        }
    }
    {
        const float4* src =
            (const float4*)(g_kproj + ((size_t)b * Kn + k0) * Hn);
#pragma unroll
        for (int i = 0; i < 4; i++) {
            int j   = tid + i * 256;
            int row = j >> 5;
            int c4  = j & 31;
            *(float4*)&sK[row][c4 * 4] = src[j];
        }
    }
    if (tid < Hn) sWvH[tid] = __float2half(wv[tid]);
    __syncthreads();

    const int wid  = tid >> 5;
    const int lane = tid & 31;
    const int gid  = lane >> 2;
    const int tig  = lane & 3;

    // 64 warp-tasks: q 0..31 x kt {0,16}; warp w takes tasks w*8 .. w*8+7.
#pragma unroll
    for (int t = 0; t < 8; t++) {
        const int task = wid * 8 + t;
        const int q    = task >> 1;
        const int kt   = (task & 1) * 16;

        float d[4] = {0.f, 0.f, 0.f, 0.f};
        const float* qrow = sQ[q];
        const float* kr0  = sK[kt + gid];
        const float* kr1  = sK[kt + gid + 8];

#pragma unroll
        for (int ht = 0; ht < 8; ht++) {
            const int h0 = ht * 16 + tig * 2;
            float2 qa  = *(const float2*)&qrow[h0];
            float2 qb  = *(const float2*)&qrow[h0 + 8];
            float2 k0a = *(const float2*)&kr0[h0];
            float2 k0b = *(const float2*)&kr0[h0 + 8];
            float2 k1a = *(const float2*)&kr1[h0];
            float2 k1b = *(const float2*)&kr1[h0 + 8];

            uint32_t a[4], bb[2];
            a[0] = tanh2(qa.y + k0a.y, qa.x + k0a.x);
            a[1] = tanh2(qa.y + k1a.y, qa.x + k1a.x);
            a[2] = tanh2(qb.y + k0b.y, qb.x + k0b.x);
            a[3] = tanh2(qb.y + k1b.y, qb.x + k1b.x);
            bb[0] = *(const uint32_t*)&sWvH[h0];
            bb[1] = *(const uint32_t*)&sWvH[h0 + 8];
            mma16816h(d, a, bb);
        }

        if (tig == 0) {
            float* srow = g_scores + ((size_t)b * Qn + qh + q) * Kn + k0 + kt;
            srow[gid]     = d[0];
            srow[gid + 8] = d[2];
        }
    }
}

// ---------------------------------------------------------------------------
// Masked softmax over K=1024, in place in g_scores.
// Invalid lanes (k >= vlen) -> exactly 0 after exp underflow.
// ---------------------------------------------------------------------------
__global__ void softmax_kernel(const int* __restrict__ vlen) {
    const int b   = blockIdx.y;
    const int q   = blockIdx.x;
    const int tid = threadIdx.x;

    float* row   = g_scores + ((size_t)b * Qn + q) * Kn;
    const int vl = vlen[b];

    float4 s      = ((const float4*)row)[tid];
    const int kb  = tid * 4;
    if (kb + 0 >= vl) s.x = -1e6f;
    if (kb + 1 >= vl) s.y = -1e6f;
    if (kb + 2 >= vl) s.z = -1e6f;
    if (kb + 3 >= vl) s.w = -1e6f;

    __shared__ float redm[8];
    __shared__ float reds[8];

    float m = fmaxf(fmaxf(s.x, s.y), fmaxf(s.z, s.w));
#pragma unroll
    for (int o = 16; o; o >>= 1) m = fmaxf(m, __shfl_xor_sync(0xffffffffu, m, o));
    if ((tid & 31) == 0) redm[tid >> 5] = m;
    __syncthreads();
    float M = redm[0];
#pragma unroll
    for (int i = 1; i < 8; i++) M = fmaxf(M, redm[i]);

    float e0 = __expf(s.x - M);
    float e1 = __expf(s.y - M);
    float e2 = __expf(s.z - M);
    float e3 = __expf(s.w - M);

    float t = (e0 + e1) + (e2 + e3);
#pragma unroll
    for (int o = 16; o; o >>= 1) t += __shfl_xor_sync(0xffffffffu, t, o);
    if ((tid & 31) == 0) reds[tid >> 5] = t;
    __syncthreads();
    float S = reds[0];
#pragma unroll
    for (int i = 1; i < 8; i++) S += reds[i];

    float inv = 1.0f / S;
    ((float4*)row)[tid] = make_float4(e0 * inv, e1 * inv, e2 * inv, e3 * inv);
}

// ---------------------------------------------------------------------------
// AV as HMMA GEMM. R11: 16 k-chunks of 64 (was 8x128) -> grid (16, Bn) = 256
// CTAs, ~2x active parallelism after vlen early-exit and finer vlen
// granularity; k-split duplicates NO staging (unlike R9's n-split).
// V staged natural [k][n] + ldmatrix + prefetch (R10 machinery).
// 8 warps 2(M) x 4(N); warp tile 32q x 64n.
// ---------------------------------------------------------------------------
__global__ void __launch_bounds__(256, 1) av_mma_kernel(
    const float* __restrict__ V, const int* __restrict__ vlen) {
    const int b  = blockIdx.y;
    const int ck = blockIdx.x;
    const int k0 = ck * 64;
    if (k0 >= vlen[b]) return;  // uniform per CTA

    __shared__ __align__(16) __nv_bfloat16 sAh[64][APAD];  // attn [q][k]
    __shared__ __align__(16) __nv_bfloat16 sAl[64][APAD];
    __shared__ __align__(16) __nv_bfloat16 sVh[32][VPAD];  // V [k][n] natural
    __shared__ __align__(16) __nv_bfloat16 sVl[32][VPAD];

    const int tid  = threadIdx.x;
    const int wid  = tid >> 5;
    const int lane = tid & 31;
    const int gid  = lane >> 2;
    const int tig  = lane & 3;
    const int lrow = lane & 15;
    const int lcol = (lane >> 4) * 8;
    const int wm   = (wid & 1) * 32;   // 2 x 32 = 64 q
    const int wn   = (wid >> 1) * 64;  // 4 x 64 = 256 dv

    float acc[2][8][4];
#pragma unroll
    for (int im = 0; im < 2; im++)
#pragma unroll
        for (int j = 0; j < 8; j++)
#pragma unroll
            for (int r = 0; r < 4; r++) acc[im][j][r] = 0.f;

    const float* Ab = g_scores + ((size_t)b * Qn) * Kn + k0;
    const float* Vb = V + ((size_t)b * Kn + k0) * DVn;

    float4 aPre[2], vPre[8];
#pragma unroll
    for (int i = 0; i < 2; i++) {
        int idx = tid + i * 256;
        int r = idx >> 3, kq = idx & 7;
        aPre[i] = *(const float4*)&Ab[(size_t)r * Kn + kq * 4];
    }
#pragma unroll
    for (int i = 0; i < 8; i++) {
        int idx = tid + i * 256;
        int k = idx >> 6, n4 = idx & 63;
        vPre[i] = *(const float4*)&Vb[(size_t)k * DVn + n4 * 4];
    }

    for (int kc = 0; kc < 64; kc += KC) {
#pragma unroll
        for (int i = 0; i < 2; i++) {
            int idx = tid + i * 256;
            int r = idx >> 3, kq = idx & 7;
            float4 v = aPre[i];
            *(__nv_bfloat162*)&sAh[r][kq * 4]     = hi2(v.x, v.y);
            *(__nv_bfloat162*)&sAh[r][kq * 4 + 2] = hi2(v.z, v.w);
            *(__nv_bfloat162*)&sAl[r][kq * 4]     = lo2(v.x, v.y);
            *(__nv_bfloat162*)&sAl[r][kq * 4 + 2] = lo2(v.z, v.w);
        }
#pragma unroll
        for (int i = 0; i < 8; i++) {
            int idx = tid + i * 256;
            int k = idx >> 6, n4 = idx & 63;
            float4 v = vPre[i];
            *(__nv_bfloat162*)&sVh[k][n4 * 4]     = hi2(v.x, v.y);
            *(__nv_bfloat162*)&sVh[k][n4 * 4 + 2] = hi2(v.z, v.w);
            *(__nv_bfloat162*)&sVl[k][n4 * 4]     = lo2(v.x, v.y);
            *(__nv_bfloat162*)&sVl[k][n4 * 4 + 2] = lo2(v.z, v.w);
        }
        __syncthreads();

        if (kc + KC < 64) {
#pragma unroll
            for (int i = 0; i < 2; i++) {
                int idx = tid + i * 256;
                int r = idx >> 3, kq = idx & 7;
                aPre[i] = *(const float4*)
                    &Ab[(size_t)r * Kn + kc + KC + kq * 4];
            }
#pragma unroll
            for (int i = 0; i < 8; i++) {
                int idx = tid + i * 256;
                int k = idx >> 6, n4 = idx & 63;
                vPre[i] = *(const float4*)
                    &Vb[(size_t)(kc + KC + k) * DVn + n4 * 4];
            }
        }

#pragma unroll
        for (int s = 0; s < 2; s++) {
            uint32_t Ah2[2][4], Al2[2][4];
#pragma unroll
            for (int im = 0; im < 2; im++) {
                ldm_x4(Ah2[im], &sAh[wm + im * 16 + lrow][s * 16 + lcol]);
                ldm_x4(Al2[im], &sAl[wm + im * 16 + lrow][s * 16 + lcol]);
            }
            uint32_t Bh[8][2], Bl[8][2];
#pragma unroll
            for (int jj = 0; jj < 4; jj++) {
                uint32_t t[4];
                ldm_x4t(t, &sVh[s * 16 + lrow][wn + jj * 16 + lcol]);
                Bh[jj * 2][0] = t[0]; Bh[jj * 2][1] = t[1];
                Bh[jj * 2 + 1][0] = t[2]; Bh[jj * 2 + 1][1] = t[3];
                ldm_x4t(t, &sVl[s * 16 + lrow][wn + jj * 16 + lcol]);
                Bl[jj * 2][0] = t[0]; Bl[jj * 2][1] = t[1];
                Bl[jj * 2 + 1][0] = t[2]; Bl[jj * 2 + 1][1] = t[3];
            }
#pragma unroll
            for (int im = 0; im < 2; im++) {
#pragma unroll
                for (int j = 0; j < 8; j++) {
                    mma16816(acc[im][j], Ah2[im], Bh[j]);
                    mma16816(acc[im][j], Al2[im], Bh[j]);
                    mma16816(acc[im][j], Ah2[im], Bl[j]);
                }
            }
        }
        __syncthreads();
    }

    float* Pb = &g_part[ck][b][0][0];
#pragma unroll
    for (int im = 0; im < 2; im++) {
        int r = wm + im * 16 + gid;
#pragma unroll
        for (int j = 0; j < 8; j++) {
            int c = wn + j * 8 + tig * 2;
            *(float2*)&Pb[(size_t)r * DVn + c] =
                make_float2(acc[im][j][0], acc[im][j][1]);
            *(float2*)&Pb[(size_t)(r + 8) * DVn + c] =
                make_float2(acc[im][j][2], acc[im][j][3]);
        }
    }
}

// ---------------------------------------------------------------------------
// out = sum over 16 k-chunk partials. 256 CTAs x 256 threads x 1 float4.
// ---------------------------------------------------------------------------
__global__ void reduce_kernel(float* __restrict__ out) {
    const int idx = blockIdx.x * 256 + threadIdx.x;
    const float4* p = (const float4*)&g_part[0][0][0][0];
    const int stride = Bn * Qn * DVn / 4;  // 65536
    float4 s = p[idx];
#pragma unroll
    for (int c = 1; c < 16; c++) {
        float4 t = p[idx + c * stride];
        s.x += t.x; s.y += t.y; s.z += t.z; s.w += t.w;
    }
    ((float4*)out)[idx] = s;
}

// ---------------------------------------------------------------------------
extern "C" void kernel_launch(void* const* d_in, const int* in_sizes, int n_in,
                              void* d_out, int out_size) {
    const float* queries = (const float*)d_in[0];
    const float* keys    = (const float*)d_in[1];
    const float* values  = (const float*)d_in[2];
    const int*   vlens   = (const int*)d_in[3];
    const float* Wq      = (const float*)d_in[4];
    const float* Wk      = (const float*)d_in[5];
    const float* wv      = (const float*)d_in[6];
    float* out           = (float*)d_out;

    proj_mma_kernel<<<136, 256>>>(keys, queries, Wk, Wq);
    scores_kernel<<<dim3(Kn / 32, 2, Bn), 256>>>(wv);
    softmax_kernel<<<dim3(Qn, Bn), 256>>>(vlens);
    av_mma_kernel<<<dim3(16, Bn), 256>>>(values, vlens);
    reduce_kernel<<<256, 256>>>(out);
}

// round 12
// speedup vs baseline: 1.1245x; 1.1245x over previous
#include <cuda_runtime.h>
#include <cuda_bf16.h>
#include <cstdint>

#define Bn  16
#define Qn  64
#define Kn  1024
#define Dn  256
#define Hn  128
#define DVn 256

// Scratch (device globals; no allocation allowed in kernel_launch)
__device__ float g_kproj[Bn * Kn * Hn];   // 8 MB
__device__ float g_qproj[Bn * Qn * Hn];   // 0.5 MB
__device__ float g_scores[Bn * Qn * Kn];  // 4 MB raw scores
__device__ float2 g_rowstat[Bn * Qn];     // per-row (max, 1/sum) for softmax

__device__ __forceinline__ float fast_tanh(float x) {
    float y;
    asm("tanh.approx.f32 %0, %1;" : "=f"(y) : "f"(x));
    return y;
}

// ---------------------------------------------------------------------------
// mma.sync m16n8k16 bf16 (row.col) fp32 accum; ldmatrix fragment loaders.
// All compute_80+ PTX (the harness's compute_100 virtual target rejects
// tcgen05; these pass).
// ---------------------------------------------------------------------------
__device__ __forceinline__ void mma16816(float* d, const uint32_t* a,
                                         const uint32_t* b) {
    asm volatile(
        "mma.sync.aligned.m16n8k16.row.col.f32.bf16.bf16.f32 "
        "{%0,%1,%2,%3}, {%4,%5,%6,%7}, {%8,%9}, {%0,%1,%2,%3};"
        : "+f"(d[0]), "+f"(d[1]), "+f"(d[2]), "+f"(d[3])
        : "r"(a[0]), "r"(a[1]), "r"(a[2]), "r"(a[3]), "r"(b[0]), "r"(b[1]));
}

__device__ __forceinline__ void ldm_x4(uint32_t* r, const __nv_bfloat16* p) {
    uint32_t a = (uint32_t)__cvta_generic_to_shared(p);
    asm volatile(
        "ldmatrix.sync.aligned.m8n8.x4.shared.b16 {%0,%1,%2,%3}, [%4];"
        : "=r"(r[0]), "=r"(r[1]), "=r"(r[2]), "=r"(r[3]) : "r"(a));
}
__device__ __forceinline__ void ldm_x4t(uint32_t* r, const __nv_bfloat16* p) {
    uint32_t a = (uint32_t)__cvta_generic_to_shared(p);
    asm volatile(
        "ldmatrix.sync.aligned.m8n8.x4.trans.shared.b16 {%0,%1,%2,%3}, [%4];"
        : "=r"(r[0]), "=r"(r[1]), "=r"(r[2]), "=r"(r[3]) : "r"(a));
}

__device__ __forceinline__ __nv_bfloat162 hi2(float a, float b) {
    return __halves2bfloat162(__float2bfloat16(a), __float2bfloat16(b));
}
__device__ __forceinline__ __nv_bfloat162 lo2(float a, float b) {
    return __halves2bfloat162(
        __float2bfloat16(a - __bfloat162float(__float2bfloat16(a))),
        __float2bfloat16(b - __bfloat162float(__float2bfloat16(b))));
}

#define KC 32
#define APAD 40   // A tiles [m][32+8]: ldmatrix phases conflict-free
#define WPAD 136  // W tile [32][128+8]: row stride 68 words mod 32 = 4
#define VPAD 264  // V tile [32][256+8]: row stride 132 words mod 32 = 4

// ---------------------------------------------------------------------------
// Projection P[r, h] = sum_d X[r, d] * W[d, h] via HMMA, split-bf16 3-product
// (R10 machinery: natural-layout staging + ldmatrix + prefetch).
// ---------------------------------------------------------------------------
__global__ void __launch_bounds__(256, 1) proj_mma_kernel(
    const float* __restrict__ keys, const float* __restrict__ queries,
    const float* __restrict__ Wk, const float* __restrict__ Wq) {
    __shared__ __align__(16) __nv_bfloat16 sAh[128][APAD];
    __shared__ __align__(16) __nv_bfloat16 sAl[128][APAD];
    __shared__ __align__(16) __nv_bfloat16 sWh[32][WPAD];  // [d][h] natural
    __shared__ __align__(16) __nv_bfloat16 sWl[32][WPAD];

    const int tid  = threadIdx.x;
    const int wid  = tid >> 5;
    const int lane = tid & 31;
    const int cid  = blockIdx.x;

    const float* X;
    const float* W;
    float* P;
    int row0;
    if (cid < 128) {
        X = keys; W = Wk; P = g_kproj; row0 = cid * 128;
    } else {
        X = queries; W = Wq; P = g_qproj; row0 = (cid - 128) * 128;
    }

    const int wm   = (wid & 1) * 64;
    const int wn   = (wid >> 1) * 32;
    const int gid  = lane >> 2;
    const int tig  = lane & 3;
    const int lrow = lane & 15;
    const int lcol = (lane >> 4) * 8;

    float acc[4][4][4];
#pragma unroll
    for (int im = 0; im < 4; im++)
#pragma unroll
        for (int j = 0; j < 4; j++)
#pragma unroll
            for (int r = 0; r < 4; r++) acc[im][j][r] = 0.f;

    float4 xPre[4], wPre[4];
#pragma unroll
    for (int i = 0; i < 4; i++) {
        int idx = tid + i * 256;
        int r = idx >> 3, kq = idx & 7;
        xPre[i] = *(const float4*)&X[(size_t)(row0 + r) * Dn + kq * 4];
    }
#pragma unroll
    for (int i = 0; i < 4; i++) {
        int idx = tid + i * 256;
        int k = idx >> 5, n4 = idx & 31;
        wPre[i] = *(const float4*)&W[(size_t)k * Hn + n4 * 4];
    }

    for (int kc = 0; kc < Dn; kc += KC) {
#pragma unroll
        for (int i = 0; i < 4; i++) {
            int idx = tid + i * 256;
            int r = idx >> 3, kq = idx & 7;
            float4 v = xPre[i];
            *(__nv_bfloat162*)&sAh[r][kq * 4]     = hi2(v.x, v.y);
            *(__nv_bfloat162*)&sAh[r][kq * 4 + 2] = hi2(v.z, v.w);
            *(__nv_bfloat162*)&sAl[r][kq * 4]     = lo2(v.x, v.y);
            *(__nv_bfloat162*)&sAl[r][kq * 4 + 2] = lo2(v.z, v.w);
        }
#pragma unroll
        for (int i = 0; i < 4; i++) {
            int idx = tid + i * 256;
            int k = idx >> 5, n4 = idx & 31;
            float4 v = wPre[i];
            *(__nv_bfloat162*)&sWh[k][n4 * 4]     = hi2(v.x, v.y);
            *(__nv_bfloat162*)&sWh[k][n4 * 4 + 2] = hi2(v.z, v.w);
            *(__nv_bfloat162*)&sWl[k][n4 * 4]     = lo2(v.x, v.y);
            *(__nv_bfloat162*)&sWl[k][n4 * 4 + 2] = lo2(v.z, v.w);
        }
        __syncthreads();

        if (kc + KC < Dn) {
#pragma unroll
            for (int i = 0; i < 4; i++) {
                int idx = tid + i * 256;
                int r = idx >> 3, kq = idx & 7;
                xPre[i] = *(const float4*)
                    &X[(size_t)(row0 + r) * Dn + kc + KC + kq * 4];
            }
#pragma unroll
            for (int i = 0; i < 4; i++) {
                int idx = tid + i * 256;
                int k = idx >> 5, n4 = idx & 31;
                wPre[i] = *(const float4*)
                    &W[(size_t)(kc + KC + k) * Hn + n4 * 4];
            }
        }

#pragma unroll
        for (int s = 0; s < 2; s++) {
            uint32_t Ah[4][4], Al[4][4];
#pragma unroll
            for (int im = 0; im < 4; im++) {
                ldm_x4(Ah[im], &sAh[wm + im * 16 + lrow][s * 16 + lcol]);
                ldm_x4(Al[im], &sAl[wm + im * 16 + lrow][s * 16 + lcol]);
            }
            uint32_t Bh[4][2], Bl[4][2];
#pragma unroll
            for (int jj = 0; jj < 2; jj++) {
                uint32_t t[4];
                ldm_x4t(t, &sWh[s * 16 + lrow][wn + jj * 16 + lcol]);
                Bh[jj * 2][0] = t[0]; Bh[jj * 2][1] = t[1];
                Bh[jj * 2 + 1][0] = t[2]; Bh[jj * 2 + 1][1] = t[3];
                ldm_x4t(t, &sWl[s * 16 + lrow][wn + jj * 16 + lcol]);
                Bl[jj * 2][0] = t[0]; Bl[jj * 2][1] = t[1];
                Bl[jj * 2 + 1][0] = t[2]; Bl[jj * 2 + 1][1] = t[3];
            }
#pragma unroll
            for (int im = 0; im < 4; im++) {
#pragma unroll
                for (int j = 0; j < 4; j++) {
                    mma16816(acc[im][j], Ah[im], Bh[j]);
                    mma16816(acc[im][j], Al[im], Bh[j]);
                    mma16816(acc[im][j], Ah[im], Bl[j]);
                }
            }
        }
        __syncthreads();
    }

#pragma unroll
    for (int im = 0; im < 4; im++) {
        int r_lo = row0 + wm + im * 16 + gid;
#pragma unroll
        for (int j = 0; j < 4; j++) {
            int c = wn + j * 8 + tig * 2;
            *(float2*)&P[(size_t)r_lo * Hn + c] =
                make_float2(acc[im][j][0], acc[im][j][1]);
            *(float2*)&P[(size_t)(r_lo + 8) * Hn + c] =
                make_float2(acc[im][j][2], acc[im][j][3]);
        }
    }
}

// ---------------------------------------------------------------------------
// scores[b, q, k] = sum_h wv[h] * tanh(qproj[b,q,h] + kproj[b,k,h])
// fp32 tanh.approx — this kernel is AT its MUFU floor (~29us); both f16x2
// variants (R9, R11) lost to operand-movement overhead. Do not revisit.
// CTA = (k-tile 32, q-half 32, b).
// ---------------------------------------------------------------------------
__global__ void scores_kernel(const float* __restrict__ wv) {
    const int b   = blockIdx.z;
    const int qh  = blockIdx.y * 32;
    const int k0  = blockIdx.x * 32;
    const int tid = threadIdx.x;

    __shared__ __align__(16) float sQ[32][Hn];
    __shared__ __align__(16) float sK[32][132];
    __shared__ __align__(16) float sWv[Hn];

    {
        const float4* src =
            (const float4*)(g_qproj + ((size_t)b * Qn + qh) * Hn);
        float4* dst = (float4*)&sQ[0][0];
#pragma unroll
        for (int i = 0; i < 4; i++) {
            int j = tid + i * 256;
            dst[j] = src[j];
        }
    }
    {
        const float4* src =
            (const float4*)(g_kproj + ((size_t)b * Kn + k0) * Hn);
#pragma unroll
        for (int i = 0; i < 4; i++) {
            int j   = tid + i * 256;
            int row = j >> 5;
            int c4  = j & 31;
            *(float4*)&sK[row][c4 * 4] = src[j];
        }
    }
    if (tid < Hn) sWv[tid] = wv[tid];
    __syncthreads();

    const int kk = tid & 31;
    const int q0 = (tid >> 5) * 4;
    float sc[4];
    sc[0] = sc[1] = sc[2] = sc[3] = 0.f;

#pragma unroll 4
    for (int h = 0; h < Hn; h += 4) {
        float4 kv = *(const float4*)&sK[kk][h];
        float4 w4 = *(const float4*)&sWv[h];
#pragma unroll
        for (int qi = 0; qi < 4; qi++) {
            float4 qv = *(const float4*)&sQ[q0 + qi][h];
            sc[qi] += w4.x * fast_tanh(qv.x + kv.x);
            sc[qi] += w4.y * fast_tanh(qv.y + kv.y);
            sc[qi] += w4.z * fast_tanh(qv.z + kv.z);
            sc[qi] += w4.w * fast_tanh(qv.w + kv.w);
        }
    }

    float* srow = g_scores + ((size_t)b * Qn + qh) * Kn + k0 + kk;
#pragma unroll
    for (int qi = 0; qi < 4; qi++) {
        srow[(size_t)(q0 + qi) * Kn] = sc[qi];
    }
}

// ---------------------------------------------------------------------------
// R12: per-row softmax statistics only — (max, 1/sum) over the masked row.
// Replaces the full softmax round-trip (8 MB rw -> 4 MB r + 8 KB w); the
// normalization itself is fused into av_mma's staging.
// ---------------------------------------------------------------------------
__global__ void rowstat_kernel(const int* __restrict__ vlen) {
    const int b   = blockIdx.y;
    const int q   = blockIdx.x;
    const int tid = threadIdx.x;

    const float* row = g_scores + ((size_t)b * Qn + q) * Kn;
    const int vl = vlen[b];

    float4 s     = ((const float4*)row)[tid];
    const int kb = tid * 4;
    if (kb + 0 >= vl) s.x = -1e6f;
    if (kb + 1 >= vl) s.y = -1e6f;
    if (kb + 2 >= vl) s.z = -1e6f;
    if (kb + 3 >= vl) s.w = -1e6f;

    __shared__ float redm[8];
    __shared__ float reds[8];

    float m = fmaxf(fmaxf(s.x, s.y), fmaxf(s.z, s.w));
#pragma unroll
    for (int o = 16; o; o >>= 1) m = fmaxf(m, __shfl_xor_sync(0xffffffffu, m, o));
    if ((tid & 31) == 0) redm[tid >> 5] = m;
    __syncthreads();
    float M = redm[0];
#pragma unroll
    for (int i = 1; i < 8; i++) M = fmaxf(M, redm[i]);

    float t = (__expf(s.x - M) + __expf(s.y - M)) +
              (__expf(s.z - M) + __expf(s.w - M));
#pragma unroll
    for (int o = 16; o; o >>= 1) t += __shfl_xor_sync(0xffffffffu, t, o);
    if ((tid & 31) == 0) reds[tid >> 5] = t;
    __syncthreads();

    if (tid == 0) {
        float S = reds[0];
#pragma unroll
        for (int i = 1; i < 8; i++) S += reds[i];
        g_rowstat[b * Qn + q] = make_float2(M, 1.0f / S);
    }
}

// ---------------------------------------------------------------------------
// Zero d_out (it is poisoned before timing; av accumulates atomically).
// ---------------------------------------------------------------------------
__global__ void zero_out_kernel(float* __restrict__ out) {
    const int idx = blockIdx.x * 256 + threadIdx.x;  // 65536 float4
    ((float4*)out)[idx] = make_float4(0.f, 0.f, 0.f, 0.f);
}

// ---------------------------------------------------------------------------
// AV as HMMA GEMM with FUSED softmax normalization.
// Grid (16 k-chunks of 64, Bn); chunks beyond vlen exit (contribute 0).
// Staging reads RAW scores and applies attn = exp(s - M) * invS with explicit
// k >= vlen -> 0 masking (matches reference exp(-1e6-M) underflow-to-0).
// Epilogue: atomicAdd into pre-zeroed out (replaces the 16 MB partials
// round-trip + reduce kernel). V staged natural [k][n] + ldmatrix + prefetch.
// 8 warps 2(M) x 4(N); warp tile 32q x 64n.
// ---------------------------------------------------------------------------
__global__ void __launch_bounds__(256, 1) av_mma_kernel(
    const float* __restrict__ V, const int* __restrict__ vlen,
    float* __restrict__ out) {
    const int b  = blockIdx.y;
    const int ck = blockIdx.x;
    const int k0 = ck * 64;
    const int vl = vlen[b];
    if (k0 >= vl) return;  // uniform per CTA

    __shared__ __align__(16) __nv_bfloat16 sAh[64][APAD];  // attn [q][k]
    __shared__ __align__(16) __nv_bfloat16 sAl[64][APAD];
    __shared__ __align__(16) __nv_bfloat16 sVh[32][VPAD];  // V [k][n] natural
    __shared__ __align__(16) __nv_bfloat16 sVl[32][VPAD];
    __shared__ __align__(8) float2 sMS[64];                // per-q (M, invS)

    const int tid  = threadIdx.x;
    const int wid  = tid >> 5;
    const int lane = tid & 31;
    const int gid  = lane >> 2;
    const int tig  = lane & 3;
    const int lrow = lane & 15;
    const int lcol = (lane >> 4) * 8;
    const int wm   = (wid & 1) * 32;   // 2 x 32 = 64 q
    const int wn   = (wid >> 1) * 64;  // 4 x 64 = 256 dv

    if (tid < 64) sMS[tid] = g_rowstat[b * Qn + tid];

    float acc[2][8][4];
#pragma unroll
    for (int im = 0; im < 2; im++)
#pragma unroll
        for (int j = 0; j < 8; j++)
#pragma unroll
            for (int r = 0; r < 4; r++) acc[im][j][r] = 0.f;

    const float* Ab = g_scores + ((size_t)b * Qn) * Kn + k0;
    const float* Vb = V + ((size_t)b * Kn + k0) * DVn;

    float4 aPre[2], vPre[8];
#pragma unroll
    for (int i = 0; i < 2; i++) {
        int idx = tid + i * 256;
        int r = idx >> 3, kq = idx & 7;
        aPre[i] = *(const float4*)&Ab[(size_t)r * Kn + kq * 4];
    }
#pragma unroll
    for (int i = 0; i < 8; i++) {
        int idx = tid + i * 256;
        int k = idx >> 6, n4 = idx & 63;
        vPre[i] = *(const float4*)&Vb[(size_t)k * DVn + n4 * 4];
    }
    __syncthreads();  // sMS visible before first staging conversion

    for (int kc = 0; kc < 64; kc += KC) {
        // ---- stage attn: apply exp(s - M) * invS with vlen masking ----
#pragma unroll
        for (int i = 0; i < 2; i++) {
            int idx = tid + i * 256;
            int r = idx >> 3, kq = idx & 7;
            float4 v = aPre[i];
            float2 ms = sMS[r];
            int kg = k0 + kc + kq * 4;
            float px = (kg + 0 < vl) ? __expf(v.x - ms.x) * ms.y : 0.f;
            float py = (kg + 1 < vl) ? __expf(v.y - ms.x) * ms.y : 0.f;
            float pz = (kg + 2 < vl) ? __expf(v.z - ms.x) * ms.y : 0.f;
            float pw = (kg + 3 < vl) ? __expf(v.w - ms.x) * ms.y : 0.f;
            *(__nv_bfloat162*)&sAh[r][kq * 4]     = hi2(px, py);
            *(__nv_bfloat162*)&sAh[r][kq * 4 + 2] = hi2(pz, pw);
            *(__nv_bfloat162*)&sAl[r][kq * 4]     = lo2(px, py);
            *(__nv_bfloat162*)&sAl[r][kq * 4 + 2] = lo2(pz, pw);
        }
#pragma unroll
        for (int i = 0; i < 8; i++) {
            int idx = tid + i * 256;
            int k = idx >> 6, n4 = idx & 63;
            float4 v = vPre[i];
            *(__nv_bfloat162*)&sVh[k][n4 * 4]     = hi2(v.x, v.y);
            *(__nv_bfloat162*)&sVh[k][n4 * 4 + 2] = hi2(v.z, v.w);
            *(__nv_bfloat162*)&sVl[k][n4 * 4]     = lo2(v.x, v.y);
            *(__nv_bfloat162*)&sVl[k][n4 * 4 + 2] = lo2(v.z, v.w);
        }
        __syncthreads();

        if (kc + KC < 64) {
#pragma unroll
            for (int i = 0; i < 2; i++) {
                int idx = tid + i * 256;
                int r = idx >> 3, kq = idx & 7;
                aPre[i] = *(const float4*)
                    &Ab[(size_t)r * Kn + kc + KC + kq * 4];
            }
#pragma unroll
            for (int i = 0; i < 8; i++) {
                int idx = tid + i * 256;
                int k = idx >> 6, n4 = idx & 63;
                vPre[i] = *(const float4*)
                    &Vb[(size_t)(kc + KC + k) * DVn + n4 * 4];
            }
        }

#pragma unroll
        for (int s = 0; s < 2; s++) {
            uint32_t Ah2[2][4], Al2[2][4];
#pragma unroll
            for (int im = 0; im < 2; im++) {
                ldm_x4(Ah2[im], &sAh[wm + im * 16 + lrow][s * 16 + lcol]);
                ldm_x4(Al2[im], &sAl[wm + im * 16 + lrow][s * 16 + lcol]);
            }
            uint32_t Bh[8][2], Bl[8][2];
#pragma unroll
            for (int jj = 0; jj < 4; jj++) {
                uint32_t t[4];
                ldm_x4t(t, &sVh[s * 16 + lrow][wn + jj * 16 + lcol]);
                Bh[jj * 2][0] = t[0]; Bh[jj * 2][1] = t[1];
                Bh[jj * 2 + 1][0] = t[2]; Bh[jj * 2 + 1][1] = t[3];
                ldm_x4t(t, &sVl[s * 16 + lrow][wn + jj * 16 + lcol]);
                Bl[jj * 2][0] = t[0]; Bl[jj * 2][1] = t[1];
                Bl[jj * 2 + 1][0] = t[2]; Bl[jj * 2 + 1][1] = t[3];
            }
#pragma unroll
            for (int im = 0; im < 2; im++) {
#pragma unroll
                for (int j = 0; j < 8; j++) {
                    mma16816(acc[im][j], Ah2[im], Bh[j]);
                    mma16816(acc[im][j], Al2[im], Bh[j]);
                    mma16816(acc[im][j], Ah2[im], Bl[j]);
                }
            }
        }
        __syncthreads();
    }

    // ---- epilogue: atomic accumulate into out ----
    float* Ob = out + ((size_t)b * Qn) * DVn;
#pragma unroll
    for (int im = 0; im < 2; im++) {
        int r = wm + im * 16 + gid;
#pragma unroll
        for (int j = 0; j < 8; j++) {
            int c = wn + j * 8 + tig * 2;
            atomicAdd(&Ob[(size_t)r * DVn + c],           acc[im][j][0]);
            atomicAdd(&Ob[(size_t)r * DVn + c + 1],       acc[im][j][1]);
            atomicAdd(&Ob[(size_t)(r + 8) * DVn + c],     acc[im][j][2]);
            atomicAdd(&Ob[(size_t)(r + 8) * DVn + c + 1], acc[im][j][3]);
        }
    }
}

// ---------------------------------------------------------------------------
extern "C" void kernel_launch(void* const* d_in, const int* in_sizes, int n_in,
                              void* d_out, int out_size) {
    const float* queries = (const float*)d_in[0];
    const float* keys    = (const float*)d_in[1];
    const float* values  = (const float*)d_in[2];
    const int*   vlens   = (const int*)d_in[3];
    const float* Wq      = (const float*)d_in[4];
    const float* Wk      = (const float*)d_in[5];
    const float* wv      = (const float*)d_in[6];
    float* out           = (float*)d_out;

    zero_out_kernel<<<Bn * Qn * DVn / 1024, 256>>>(out);
    proj_mma_kernel<<<136, 256>>>(keys, queries, Wk, Wq);
    scores_kernel<<<dim3(Kn / 32, 2, Bn), 256>>>(wv);
    rowstat_kernel<<<dim3(Qn, Bn), 256>>>(vlens);
    av_mma_kernel<<<dim3(16, Bn), 256>>>(values, vlens, out);
}

// round 13
// speedup vs baseline: 1.1613x; 1.0328x over previous
#include <cuda_runtime.h>
#include <cuda_bf16.h>
#include <cstdint>

#define Bn  16
#define Qn  64
#define Kn  1024
#define Dn  256
#define Hn  128
#define DVn 256

// Scratch (device globals; no allocation allowed in kernel_launch)
__device__ float g_kproj[Bn * Kn * Hn];   // 8 MB
__device__ float g_qproj[Bn * Qn * Hn];   // 0.5 MB
__device__ float g_escores[Bn * Qn * Kn]; // 4 MB: exp(score), masked -> 0
__device__ float g_rowsum[Bn * Qn];       // per-row sum of exp (atomic)

__device__ __forceinline__ float fast_tanh(float x) {
    float y;
    asm("tanh.approx.f32 %0, %1;" : "=f"(y) : "f"(x));
    return y;
}

// ---------------------------------------------------------------------------
// mma.sync m16n8k16 bf16 (row.col) fp32 accum; ldmatrix fragment loaders.
// All compute_80+ PTX (the harness's compute_100 virtual target rejects
// tcgen05; these pass).
// ---------------------------------------------------------------------------
__device__ __forceinline__ void mma16816(float* d, const uint32_t* a,
                                         const uint32_t* b) {
    asm volatile(
        "mma.sync.aligned.m16n8k16.row.col.f32.bf16.bf16.f32 "
        "{%0,%1,%2,%3}, {%4,%5,%6,%7}, {%8,%9}, {%0,%1,%2,%3};"
        : "+f"(d[0]), "+f"(d[1]), "+f"(d[2]), "+f"(d[3])
        : "r"(a[0]), "r"(a[1]), "r"(a[2]), "r"(a[3]), "r"(b[0]), "r"(b[1]));
}

__device__ __forceinline__ void ldm_x4(uint32_t* r, const __nv_bfloat16* p) {
    uint32_t a = (uint32_t)__cvta_generic_to_shared(p);
    asm volatile(
        "ldmatrix.sync.aligned.m8n8.x4.shared.b16 {%0,%1,%2,%3}, [%4];"
        : "=r"(r[0]), "=r"(r[1]), "=r"(r[2]), "=r"(r[3]) : "r"(a));
}
__device__ __forceinline__ void ldm_x4t(uint32_t* r, const __nv_bfloat16* p) {
    uint32_t a = (uint32_t)__cvta_generic_to_shared(p);
    asm volatile(
        "ldmatrix.sync.aligned.m8n8.x4.trans.shared.b16 {%0,%1,%2,%3}, [%4];"
        : "=r"(r[0]), "=r"(r[1]), "=r"(r[2]), "=r"(r[3]) : "r"(a));
}

__device__ __forceinline__ __nv_bfloat162 hi2(float a, float b) {
    return __halves2bfloat162(__float2bfloat16(a), __float2bfloat16(b));
}
__device__ __forceinline__ __nv_bfloat162 lo2(float a, float b) {
    return __halves2bfloat162(
        __float2bfloat16(a - __bfloat162float(__float2bfloat16(a))),
        __float2bfloat16(b - __bfloat162float(__float2bfloat16(b))));
}

#define KC 32
#define APAD 40   // A tiles [m][32+8]: ldmatrix phases conflict-free
#define WPAD 136  // W tile [32][128+8]: row stride 68 words mod 32 = 4
#define VPAD 264  // V tile [32][256+8]: row stride 132 words mod 32 = 4

// ---------------------------------------------------------------------------
// Projection P[r, h] = sum_d X[r, d] * W[d, h] via HMMA, split-bf16 3-product
// (R10 machinery: natural-layout staging + ldmatrix + prefetch).
// ---------------------------------------------------------------------------
__global__ void __launch_bounds__(256, 1) proj_mma_kernel(
    const float* __restrict__ keys, const float* __restrict__ queries,
    const float* __restrict__ Wk, const float* __restrict__ Wq) {
    __shared__ __align__(16) __nv_bfloat16 sAh[128][APAD];
    __shared__ __align__(16) __nv_bfloat16 sAl[128][APAD];
    __shared__ __align__(16) __nv_bfloat16 sWh[32][WPAD];  // [d][h] natural
    __shared__ __align__(16) __nv_bfloat16 sWl[32][WPAD];

    const int tid  = threadIdx.x;
    const int wid  = tid >> 5;
    const int lane = tid & 31;
    const int cid  = blockIdx.x;

    const float* X;
    const float* W;
    float* P;
    int row0;
    if (cid < 128) {
        X = keys; W = Wk; P = g_kproj; row0 = cid * 128;
    } else {
        X = queries; W = Wq; P = g_qproj; row0 = (cid - 128) * 128;
    }

    const int wm   = (wid & 1) * 64;
    const int wn   = (wid >> 1) * 32;
    const int gid  = lane >> 2;
    const int tig  = lane & 3;
    const int lrow = lane & 15;
    const int lcol = (lane >> 4) * 8;

    float acc[4][4][4];
#pragma unroll
    for (int im = 0; im < 4; im++)
#pragma unroll
        for (int j = 0; j < 4; j++)
#pragma unroll
            for (int r = 0; r < 4; r++) acc[im][j][r] = 0.f;

    float4 xPre[4], wPre[4];
#pragma unroll
    for (int i = 0; i < 4; i++) {
        int idx = tid + i * 256;
        int r = idx >> 3, kq = idx & 7;
        xPre[i] = *(const float4*)&X[(size_t)(row0 + r) * Dn + kq * 4];
    }
#pragma unroll
    for (int i = 0; i < 4; i++) {
        int idx = tid + i * 256;
        int k = idx >> 5, n4 = idx & 31;
        wPre[i] = *(const float4*)&W[(size_t)k * Hn + n4 * 4];
    }

    for (int kc = 0; kc < Dn; kc += KC) {
#pragma unroll
        for (int i = 0; i < 4; i++) {
            int idx = tid + i * 256;
            int r = idx >> 3, kq = idx & 7;
            float4 v = xPre[i];
            *(__nv_bfloat162*)&sAh[r][kq * 4]     = hi2(v.x, v.y);
            *(__nv_bfloat162*)&sAh[r][kq * 4 + 2] = hi2(v.z, v.w);
            *(__nv_bfloat162*)&sAl[r][kq * 4]     = lo2(v.x, v.y);
            *(__nv_bfloat162*)&sAl[r][kq * 4 + 2] = lo2(v.z, v.w);
        }
#pragma unroll
        for (int i = 0; i < 4; i++) {
            int idx = tid + i * 256;
            int k = idx >> 5, n4 = idx & 31;
            float4 v = wPre[i];
            *(__nv_bfloat162*)&sWh[k][n4 * 4]     = hi2(v.x, v.y);
            *(__nv_bfloat162*)&sWh[k][n4 * 4 + 2] = hi2(v.z, v.w);
            *(__nv_bfloat162*)&sWl[k][n4 * 4]     = lo2(v.x, v.y);
            *(__nv_bfloat162*)&sWl[k][n4 * 4 + 2] = lo2(v.z, v.w);
        }
        __syncthreads();

        if (kc + KC < Dn) {
#pragma unroll
            for (int i = 0; i < 4; i++) {
                int idx = tid + i * 256;
                int r = idx >> 3, kq = idx & 7;
                xPre[i] = *(const float4*)
                    &X[(size_t)(row0 + r) * Dn + kc + KC + kq * 4];
            }
#pragma unroll
            for (int i = 0; i < 4; i++) {
                int idx = tid + i * 256;
                int k = idx >> 5, n4 = idx & 31;
                wPre[i] = *(const float4*)
                    &W[(size_t)(kc + KC + k) * Hn + n4 * 4];
            }
        }

#pragma unroll
        for (int s = 0; s < 2; s++) {
            uint32_t Ah[4][4], Al[4][4];
#pragma unroll
            for (int im = 0; im < 4; im++) {
                ldm_x4(Ah[im], &sAh[wm + im * 16 + lrow][s * 16 + lcol]);
                ldm_x4(Al[im], &sAl[wm + im * 16 + lrow][s * 16 + lcol]);
            }
            uint32_t Bh[4][2], Bl[4][2];
#pragma unroll
            for (int jj = 0; jj < 2; jj++) {
                uint32_t t[4];
                ldm_x4t(t, &sWh[s * 16 + lrow][wn + jj * 16 + lcol]);
                Bh[jj * 2][0] = t[0]; Bh[jj * 2][1] = t[1];
                Bh[jj * 2 + 1][0] = t[2]; Bh[jj * 2 + 1][1] = t[3];
                ldm_x4t(t, &sWl[s * 16 + lrow][wn + jj * 16 + lcol]);
                Bl[jj * 2][0] = t[0]; Bl[jj * 2][1] = t[1];
                Bl[jj * 2 + 1][0] = t[2]; Bl[jj * 2 + 1][1] = t[3];
            }
#pragma unroll
            for (int im = 0; im < 4; im++) {
#pragma unroll
                for (int j = 0; j < 4; j++) {
                    mma16816(acc[im][j], Ah[im], Bh[j]);
                    mma16816(acc[im][j], Al[im], Bh[j]);
                    mma16816(acc[im][j], Ah[im], Bl[j]);
                }
            }
        }
        __syncthreads();
    }

#pragma unroll
    for (int im = 0; im < 4; im++) {
        int r_lo = row0 + wm + im * 16 + gid;
#pragma unroll
        for (int j = 0; j < 4; j++) {
            int c = wn + j * 8 + tig * 2;
            *(float2*)&P[(size_t)r_lo * Hn + c] =
                make_float2(acc[im][j][0], acc[im][j][1]);
            *(float2*)&P[(size_t)(r_lo + 8) * Hn + c] =
                make_float2(acc[im][j][2], acc[im][j][3]);
        }
    }
}

// ---------------------------------------------------------------------------
// R13: scores kernel now emits exp(score) directly (no max subtraction —
// |score| <~ 4 since |wv|~1/sqrt(128) and |tanh|<1, so exp can't overflow;
// matches reference softmax to ~1e-7) with k >= vlen masked to exactly 0,
// and atomically accumulates per-row sums. Kills the rowstat pass (5.4us).
// Within a warp all 32 lanes share the same 4 q's (lane = k), so the row
// sum is 4 shuffle reductions + 4 atomicAdds per warp.
// fp32 tanh.approx — at its MUFU floor; f16x2 lost twice (R9, R11).
// CTA = (k-tile 32, q-half 32, b).
// ---------------------------------------------------------------------------
__global__ void scores_kernel(const float* __restrict__ wv,
                              const int* __restrict__ vlen) {
    const int b   = blockIdx.z;
    const int qh  = blockIdx.y * 32;
    const int k0  = blockIdx.x * 32;
    const int tid = threadIdx.x;

    __shared__ __align__(16) float sQ[32][Hn];
    __shared__ __align__(16) float sK[32][132];
    __shared__ __align__(16) float sWv[Hn];

    {
        const float4* src =
            (const float4*)(g_qproj + ((size_t)b * Qn + qh) * Hn);
        float4* dst = (float4*)&sQ[0][0];
#pragma unroll
        for (int i = 0; i < 4; i++) {
            int j = tid + i * 256;
            dst[j] = src[j];
        }
    }
    {
        const float4* src =
            (const float4*)(g_kproj + ((size_t)b * Kn + k0) * Hn);
#pragma unroll
        for (int i = 0; i < 4; i++) {
            int j   = tid + i * 256;
            int row = j >> 5;
            int c4  = j & 31;
            *(float4*)&sK[row][c4 * 4] = src[j];
        }
    }
    if (tid < Hn) sWv[tid] = wv[tid];
    __syncthreads();

    const int kk = tid & 31;
    const int q0 = (tid >> 5) * 4;
    float sc[4];
    sc[0] = sc[1] = sc[2] = sc[3] = 0.f;

#pragma unroll 4
    for (int h = 0; h < Hn; h += 4) {
        float4 kv = *(const float4*)&sK[kk][h];
        float4 w4 = *(const float4*)&sWv[h];
#pragma unroll
        for (int qi = 0; qi < 4; qi++) {
            float4 qv = *(const float4*)&sQ[q0 + qi][h];
            sc[qi] += w4.x * fast_tanh(qv.x + kv.x);
            sc[qi] += w4.y * fast_tanh(qv.y + kv.y);
            sc[qi] += w4.z * fast_tanh(qv.z + kv.z);
            sc[qi] += w4.w * fast_tanh(qv.w + kv.w);
        }
    }

    const bool valid = (k0 + kk) < vlen[b];
    float* srow = g_escores + ((size_t)b * Qn + qh) * Kn + k0 + kk;
#pragma unroll
    for (int qi = 0; qi < 4; qi++) {
        float e = valid ? __expf(sc[qi]) : 0.f;
        srow[(size_t)(q0 + qi) * Kn] = e;
        // row-sum reduction across the warp's 32 k-lanes
        float t = e;
#pragma unroll
        for (int o = 16; o; o >>= 1) t += __shfl_xor_sync(0xffffffffu, t, o);
        if (kk == 0) atomicAdd(&g_rowsum[b * Qn + qh + q0 + qi], t);
    }
}

// ---------------------------------------------------------------------------
// Zero d_out (poisoned before timing; av accumulates atomically) and
// g_rowsum (accumulated atomically every call — graph replay safe).
// ---------------------------------------------------------------------------
__global__ void zero_out_kernel(float* __restrict__ out) {
    const int idx = blockIdx.x * 256 + threadIdx.x;  // 65536 float4
    ((float4*)out)[idx] = make_float4(0.f, 0.f, 0.f, 0.f);
    if (idx < Bn * Qn / 4) {
        ((float4*)g_rowsum)[idx] = make_float4(0.f, 0.f, 0.f, 0.f);
    }
}

// ---------------------------------------------------------------------------
// AV as HMMA GEMM with fused normalization: attn = escore * (1/rowsum).
// Grid (16 k-chunks of 64, Bn); chunks beyond vlen exit (escore there is 0
// anyway). Staging is a pure multiply now (no exp, no masking).
// Epilogue: atomicAdd into pre-zeroed out. V staged natural [k][n] +
// ldmatrix + prefetch. 8 warps 2(M) x 4(N); warp tile 32q x 64n.
// ---------------------------------------------------------------------------
__global__ void __launch_bounds__(256, 1) av_mma_kernel(
    const float* __restrict__ V, const int* __restrict__ vlen,
    float* __restrict__ out) {
    const int b  = blockIdx.y;
    const int ck = blockIdx.x;
    const int k0 = ck * 64;
    if (k0 >= vlen[b]) return;  // uniform per CTA

    __shared__ __align__(16) __nv_bfloat16 sAh[64][APAD];  // attn [q][k]
    __shared__ __align__(16) __nv_bfloat16 sAl[64][APAD];
    __shared__ __align__(16) __nv_bfloat16 sVh[32][VPAD];  // V [k][n] natural
    __shared__ __align__(16) __nv_bfloat16 sVl[32][VPAD];
    __shared__ float sIS[64];                              // per-q 1/rowsum

    const int tid  = threadIdx.x;
    const int wid  = tid >> 5;
    const int lane = tid & 31;
    const int gid  = lane >> 2;
    const int tig  = lane & 3;
    const int lrow = lane & 15;
    const int lcol = (lane >> 4) * 8;
    const int wm   = (wid & 1) * 32;   // 2 x 32 = 64 q
    const int wn   = (wid >> 1) * 64;  // 4 x 64 = 256 dv

    if (tid < 64) sIS[tid] = 1.0f / g_rowsum[b * Qn + tid];

    float acc[2][8][4];
#pragma unroll
    for (int im = 0; im < 2; im++)
#pragma unroll
        for (int j = 0; j < 8; j++)
#pragma unroll
            for (int r = 0; r < 4; r++) acc[im][j][r] = 0.f;

    const float* Ab = g_escores + ((size_t)b * Qn) * Kn + k0;
    const float* Vb = V + ((size_t)b * Kn + k0) * DVn;

    float4 aPre[2], vPre[8];
#pragma unroll
    for (int i = 0; i < 2; i++) {
        int idx = tid + i * 256;
        int r = idx >> 3, kq = idx & 7;
        aPre[i] = *(const float4*)&Ab[(size_t)r * Kn + kq * 4];
    }
#pragma unroll
    for (int i = 0; i < 8; i++) {
        int idx = tid + i * 256;
        int k = idx >> 6, n4 = idx & 63;
        vPre[i] = *(const float4*)&Vb[(size_t)k * DVn + n4 * 4];
    }
    __syncthreads();  // sIS visible before first staging conversion

    for (int kc = 0; kc < 64; kc += KC) {
#pragma unroll
        for (int i = 0; i < 2; i++) {
            int idx = tid + i * 256;
            int r = idx >> 3, kq = idx & 7;
            float4 v = aPre[i];
            float is = sIS[r];
            float px = v.x * is, py = v.y * is;
            float pz = v.z * is, pw = v.w * is;
            *(__nv_bfloat162*)&sAh[r][kq * 4]     = hi2(px, py);
            *(__nv_bfloat162*)&sAh[r][kq * 4 + 2] = hi2(pz, pw);
            *(__nv_bfloat162*)&sAl[r][kq * 4]     = lo2(px, py);
            *(__nv_bfloat162*)&sAl[r][kq * 4 + 2] = lo2(pz, pw);
        }
#pragma unroll
        for (int i = 0; i < 8; i++) {
            int idx = tid + i * 256;
            int k = idx >> 6, n4 = idx & 63;
            float4 v = vPre[i];
            *(__nv_bfloat162*)&sVh[k][n4 * 4]     = hi2(v.x, v.y);
            *(__nv_bfloat162*)&sVh[k][n4 * 4 + 2] = hi2(v.z, v.w);
            *(__nv_bfloat162*)&sVl[k][n4 * 4]     = lo2(v.x, v.y);
            *(__nv_bfloat162*)&sVl[k][n4 * 4 + 2] = lo2(v.z, v.w);
        }
        __syncthreads();

        if (kc + KC < 64) {
#pragma unroll
            for (int i = 0; i < 2; i++) {
                int idx = tid + i * 256;
                int r = idx >> 3, kq = idx & 7;
                aPre[i] = *(const float4*)
                    &Ab[(size_t)r * Kn + kc + KC + kq * 4];
            }
#pragma unroll
            for (int i = 0; i < 8; i++) {
                int idx = tid + i * 256;
                int k = idx >> 6, n4 = idx & 63;
                vPre[i] = *(const float4*)
                    &Vb[(size_t)(kc + KC + k) * DVn + n4 * 4];
            }
        }

#pragma unroll
        for (int s = 0; s < 2; s++) {
            uint32_t Ah2[2][4], Al2[2][4];
#pragma unroll
            for (int im = 0; im < 2; im++) {
                ldm_x4(Ah2[im], &sAh[wm + im * 16 + lrow][s * 16 + lcol]);
                ldm_x4(Al2[im], &sAl[wm + im * 16 + lrow][s * 16 + lcol]);
            }
            uint32_t Bh[8][2], Bl[8][2];
#pragma unroll
            for (int jj = 0; jj < 4; jj++) {
                uint32_t t[4];
                ldm_x4t(t, &sVh[s * 16 + lrow][wn + jj * 16 + lcol]);
                Bh[jj * 2][0] = t[0]; Bh[jj * 2][1] = t[1];
                Bh[jj * 2 + 1][0] = t[2]; Bh[jj * 2 + 1][1] = t[3];
                ldm_x4t(t, &sVl[s * 16 + lrow][wn + jj * 16 + lcol]);
                Bl[jj * 2][0] = t[0]; Bl[jj * 2][1] = t[1];
                Bl[jj * 2 + 1][0] = t[2]; Bl[jj * 2 + 1][1] = t[3];
            }
#pragma unroll
            for (int im = 0; im < 2; im++) {
#pragma unroll
                for (int j = 0; j < 8; j++) {
                    mma16816(acc[im][j], Ah2[im], Bh[j]);
                    mma16816(acc[im][j], Al2[im], Bh[j]);
                    mma16816(acc[im][j], Ah2[im], Bl[j]);
                }
            }
        }
        __syncthreads();
    }

    float* Ob = out + ((size_t)b * Qn) * DVn;
#pragma unroll
    for (int im = 0; im < 2; im++) {
        int r = wm + im * 16 + gid;
#pragma unroll
        for (int j = 0; j < 8; j++) {
            int c = wn + j * 8 + tig * 2;
            atomicAdd(&Ob[(size_t)r * DVn + c],           acc[im][j][0]);
            atomicAdd(&Ob[(size_t)r * DVn + c + 1],       acc[im][j][1]);
            atomicAdd(&Ob[(size_t)(r + 8) * DVn + c],     acc[im][j][2]);
            atomicAdd(&Ob[(size_t)(r + 8) * DVn + c + 1], acc[im][j][3]);
        }
    }
}

// ---------------------------------------------------------------------------
extern "C" void kernel_launch(void* const* d_in, const int* in_sizes, int n_in,
                              void* d_out, int out_size) {
    const float* queries = (const float*)d_in[0];
    const float* keys    = (const float*)d_in[1];
    const float* values  = (const float*)d_in[2];
    const int*   vlens   = (const int*)d_in[3];
    const float* Wq      = (const float*)d_in[4];
    const float* Wk      = (const float*)d_in[5];
    const float* wv      = (const float*)d_in[6];
    float* out           = (float*)d_out;

    zero_out_kernel<<<Bn * Qn * DVn / 1024, 256>>>(out);
    proj_mma_kernel<<<136, 256>>>(keys, queries, Wk, Wq);
    scores_kernel<<<dim3(Kn / 32, 2, Bn), 256>>>(wv, vlens);
    av_mma_kernel<<<dim3(16, Bn), 256>>>(values, vlens, out);
}

// round 14
// speedup vs baseline: 1.3657x; 1.1761x over previous
#include <cuda_runtime.h>
#include <cuda_bf16.h>
#include <cstdint>

#define Bn  16
#define Qn  64
#define Kn  1024
#define Dn  256
#define Hn  128
#define DVn 256

// Scratch (device globals; no allocation allowed in kernel_launch)
__device__ float g_kproj[Bn * Kn * Hn];   // 8 MB (rows >= ceil64(vlen) stay 0)
__device__ float g_qproj[Bn * Qn * Hn];   // 0.5 MB
__device__ float g_escores[Bn * Qn * Kn]; // 4 MB: exp(score), masked -> 0
                                          // (64-chunks >= vlen never written
                                          //  AND never read -> deterministic)
__device__ float g_rowsum[Bn * Qn];       // per-row sum of exp (atomic)

__device__ __forceinline__ float fast_tanh(float x) {
    float y;
    asm("tanh.approx.f32 %0, %1;" : "=f"(y) : "f"(x));
    return y;
}

// ---------------------------------------------------------------------------
// mma.sync m16n8k16 bf16 (row.col) fp32 accum; ldmatrix fragment loaders.
// All compute_80+ PTX (the harness's compute_100 virtual target rejects
// tcgen05; these pass).
// ---------------------------------------------------------------------------
__device__ __forceinline__ void mma16816(float* d, const uint32_t* a,
                                         const uint32_t* b) {
    asm volatile(
        "mma.sync.aligned.m16n8k16.row.col.f32.bf16.bf16.f32 "
        "{%0,%1,%2,%3}, {%4,%5,%6,%7}, {%8,%9}, {%0,%1,%2,%3};"
        : "+f"(d[0]), "+f"(d[1]), "+f"(d[2]), "+f"(d[3])
        : "r"(a[0]), "r"(a[1]), "r"(a[2]), "r"(a[3]), "r"(b[0]), "r"(b[1]));
}

__device__ __forceinline__ void ldm_x4(uint32_t* r, const __nv_bfloat16* p) {
    uint32_t a = (uint32_t)__cvta_generic_to_shared(p);
    asm volatile(
        "ldmatrix.sync.aligned.m8n8.x4.shared.b16 {%0,%1,%2,%3}, [%4];"
        : "=r"(r[0]), "=r"(r[1]), "=r"(r[2]), "=r"(r[3]) : "r"(a));
}
__device__ __forceinline__ void ldm_x4t(uint32_t* r, const __nv_bfloat16* p) {
    uint32_t a = (uint32_t)__cvta_generic_to_shared(p);
    asm volatile(
        "ldmatrix.sync.aligned.m8n8.x4.trans.shared.b16 {%0,%1,%2,%3}, [%4];"
        : "=r"(r[0]), "=r"(r[1]), "=r"(r[2]), "=r"(r[3]) : "r"(a));
}

__device__ __forceinline__ __nv_bfloat162 hi2(float a, float b) {
    return __halves2bfloat162(__float2bfloat16(a), __float2bfloat16(b));
}
__device__ __forceinline__ __nv_bfloat162 lo2(float a, float b) {
    return __halves2bfloat162(
        __float2bfloat16(a - __bfloat162float(__float2bfloat16(a))),
        __float2bfloat16(b - __bfloat162float(__float2bfloat16(b))));
}

#define KC 32
#define APAD 40   // A tiles [m][32+8]: ldmatrix phases conflict-free
#define WPAD 136  // W tile [32][128+8]: row stride 68 words mod 32 = 4
#define VPAD 264  // V tile [32][256+8]: row stride 132 words mod 32 = 4

// ---------------------------------------------------------------------------
// Projection P[r, h] = sum_d X[r, d] * W[d, h] via HMMA, split-bf16 3-product
// (R10 machinery). R14: kproj CTAs whose rows lie entirely >= ceil64(vlen[b])
// exit — no live scores tile ever reads them (rows between vlen and the tile
// boundary feed only predicate-masked lanes). Halves proj work on average.
// ---------------------------------------------------------------------------
__global__ void __launch_bounds__(256, 1) proj_mma_kernel(
    const float* __restrict__ keys, const float* __restrict__ queries,
    const float* __restrict__ Wk, const float* __restrict__ Wq,
    const int* __restrict__ vlen) {
    __shared__ __align__(16) __nv_bfloat16 sAh[128][APAD];
    __shared__ __align__(16) __nv_bfloat16 sAl[128][APAD];
    __shared__ __align__(16) __nv_bfloat16 sWh[32][WPAD];  // [d][h] natural
    __shared__ __align__(16) __nv_bfloat16 sWl[32][WPAD];

    const int tid  = threadIdx.x;
    const int wid  = tid >> 5;
    const int lane = tid & 31;
    const int cid  = blockIdx.x;

    const float* X;
    const float* W;
    float* P;
    int row0;
    if (cid < 128) {
        // kproj: 8 CTAs per batch; skip blocks past the masked boundary.
        const int b     = cid >> 3;
        const int local = (cid & 7) * 128;
        if (local >= ((vlen[b] + 63) & ~63)) return;
        X = keys; W = Wk; P = g_kproj; row0 = cid * 128;
    } else {
        X = queries; W = Wq; P = g_qproj; row0 = (cid - 128) * 128;
    }

    const int wm   = (wid & 1) * 64;
    const int wn   = (wid >> 1) * 32;
    const int gid  = lane >> 2;
    const int tig  = lane & 3;
    const int lrow = lane & 15;
    const int lcol = (lane >> 4) * 8;

    float acc[4][4][4];
#pragma unroll
    for (int im = 0; im < 4; im++)
#pragma unroll
        for (int j = 0; j < 4; j++)
#pragma unroll
            for (int r = 0; r < 4; r++) acc[im][j][r] = 0.f;

    float4 xPre[4], wPre[4];
#pragma unroll
    for (int i = 0; i < 4; i++) {
        int idx = tid + i * 256;
        int r = idx >> 3, kq = idx & 7;
        xPre[i] = *(const float4*)&X[(size_t)(row0 + r) * Dn + kq * 4];
    }
#pragma unroll
    for (int i = 0; i < 4; i++) {
        int idx = tid + i * 256;
        int k = idx >> 5, n4 = idx & 31;
        wPre[i] = *(const float4*)&W[(size_t)k * Hn + n4 * 4];
    }

    for (int kc = 0; kc < Dn; kc += KC) {
#pragma unroll
        for (int i = 0; i < 4; i++) {
            int idx = tid + i * 256;
            int r = idx >> 3, kq = idx & 7;
            float4 v = xPre[i];
            *(__nv_bfloat162*)&sAh[r][kq * 4]     = hi2(v.x, v.y);
            *(__nv_bfloat162*)&sAh[r][kq * 4 + 2] = hi2(v.z, v.w);
            *(__nv_bfloat162*)&sAl[r][kq * 4]     = lo2(v.x, v.y);
            *(__nv_bfloat162*)&sAl[r][kq * 4 + 2] = lo2(v.z, v.w);
        }
#pragma unroll
        for (int i = 0; i < 4; i++) {
            int idx = tid + i * 256;
            int k = idx >> 5, n4 = idx & 31;
            float4 v = wPre[i];
            *(__nv_bfloat162*)&sWh[k][n4 * 4]     = hi2(v.x, v.y);
            *(__nv_bfloat162*)&sWh[k][n4 * 4 + 2] = hi2(v.z, v.w);
            *(__nv_bfloat162*)&sWl[k][n4 * 4]     = lo2(v.x, v.y);
            *(__nv_bfloat162*)&sWl[k][n4 * 4 + 2] = lo2(v.z, v.w);
        }
        __syncthreads();

        if (kc + KC < Dn) {
#pragma unroll
            for (int i = 0; i < 4; i++) {
                int idx = tid + i * 256;
                int r = idx >> 3, kq = idx & 7;
                xPre[i] = *(const float4*)
                    &X[(size_t)(row0 + r) * Dn + kc + KC + kq * 4];
            }
#pragma unroll
            for (int i = 0; i < 4; i++) {
                int idx = tid + i * 256;
                int k = idx >> 5, n4 = idx & 31;
                wPre[i] = *(const float4*)
                    &W[(size_t)(kc + KC + k) * Hn + n4 * 4];
            }
        }

#pragma unroll
        for (int s = 0; s < 2; s++) {
            uint32_t Ah[4][4], Al[4][4];
#pragma unroll
            for (int im = 0; im < 4; im++) {
                ldm_x4(Ah[im], &sAh[wm + im * 16 + lrow][s * 16 + lcol]);
                ldm_x4(Al[im], &sAl[wm + im * 16 + lrow][s * 16 + lcol]);
            }
            uint32_t Bh[4][2], Bl[4][2];
#pragma unroll
            for (int jj = 0; jj < 2; jj++) {
                uint32_t t[4];
                ldm_x4t(t, &sWh[s * 16 + lrow][wn + jj * 16 + lcol]);
                Bh[jj * 2][0] = t[0]; Bh[jj * 2][1] = t[1];
                Bh[jj * 2 + 1][0] = t[2]; Bh[jj * 2 + 1][1] = t[3];
                ldm_x4t(t, &sWl[s * 16 + lrow][wn + jj * 16 + lcol]);
                Bl[jj * 2][0] = t[0]; Bl[jj * 2][1] = t[1];
                Bl[jj * 2 + 1][0] = t[2]; Bl[jj * 2 + 1][1] = t[3];
            }
#pragma unroll
            for (int im = 0; im < 4; im++) {
#pragma unroll
                for (int j = 0; j < 4; j++) {
                    mma16816(acc[im][j], Ah[im], Bh[j]);
                    mma16816(acc[im][j], Al[im], Bh[j]);
                    mma16816(acc[im][j], Ah[im], Bl[j]);
                }
            }
        }
        __syncthreads();
    }

#pragma unroll
    for (int im = 0; im < 4; im++) {
        int r_lo = row0 + wm + im * 16 + gid;
#pragma unroll
        for (int j = 0; j < 4; j++) {
            int c = wn + j * 8 + tig * 2;
            *(float2*)&P[(size_t)r_lo * Hn + c] =
                make_float2(acc[im][j][0], acc[im][j][1]);
            *(float2*)&P[(size_t)(r_lo + 8) * Hn + c] =
                make_float2(acc[im][j][2], acc[im][j][3]);
        }
    }
}

// ---------------------------------------------------------------------------
// scores: emits exp(score) (no max subtraction — |score| <~ 4) with
// k >= vlen masked to exactly 0; atomic per-row sums.
// R14 early-exit: CTAs whose 64-chunk starts >= vlen return immediately
// (av never reads those escores). Dead 32-tiles INSIDE a live 64-chunk
// write zeros (av does read them). Halves the tanh work on average.
// fp32 tanh.approx — at its MUFU floor; f16x2 lost twice (R9, R11).
// CTA = (k-tile 32, q-half 32, b).
// ---------------------------------------------------------------------------
__global__ void scores_kernel(const float* __restrict__ wv,
                              const int* __restrict__ vlen) {
    const int b   = blockIdx.z;
    const int qh  = blockIdx.y * 32;
    const int k0  = blockIdx.x * 32;
    const int tid = threadIdx.x;

    const int vl = vlen[b];
    if ((k0 & ~63) >= vl) return;  // whole 64-chunk dead: never read by av

    const int kk = tid & 31;
    const int q0 = (tid >> 5) * 4;
    float* srow = g_escores + ((size_t)b * Qn + qh) * Kn + k0 + kk;

    if (k0 >= vl) {
        // dead 32-tile inside a live 64-chunk: av reads it -> zero it
#pragma unroll
        for (int qi = 0; qi < 4; qi++) {
            srow[(size_t)(q0 + qi) * Kn] = 0.f;
        }
        return;
    }

    __shared__ __align__(16) float sQ[32][Hn];
    __shared__ __align__(16) float sK[32][132];
    __shared__ __align__(16) float sWv[Hn];

    {
        const float4* src =
            (const float4*)(g_qproj + ((size_t)b * Qn + qh) * Hn);
        float4* dst = (float4*)&sQ[0][0];
#pragma unroll
        for (int i = 0; i < 4; i++) {
            int j = tid + i * 256;
            dst[j] = src[j];
        }
    }
    {
        const float4* src =
            (const float4*)(g_kproj + ((size_t)b * Kn + k0) * Hn);
#pragma unroll
        for (int i = 0; i < 4; i++) {
            int j   = tid + i * 256;
            int row = j >> 5;
            int c4  = j & 31;
            *(float4*)&sK[row][c4 * 4] = src[j];
        }
    }
    if (tid < Hn) sWv[tid] = wv[tid];
    __syncthreads();

    float sc[4];
    sc[0] = sc[1] = sc[2] = sc[3] = 0.f;

#pragma unroll 4
    for (int h = 0; h < Hn; h += 4) {
        float4 kv = *(const float4*)&sK[kk][h];
        float4 w4 = *(const float4*)&sWv[h];
#pragma unroll
        for (int qi = 0; qi < 4; qi++) {
            float4 qv = *(const float4*)&sQ[q0 + qi][h];
            sc[qi] += w4.x * fast_tanh(qv.x + kv.x);
            sc[qi] += w4.y * fast_tanh(qv.y + kv.y);
            sc[qi] += w4.z * fast_tanh(qv.z + kv.z);
            sc[qi] += w4.w * fast_tanh(qv.w + kv.w);
        }
    }

    const bool valid = (k0 + kk) < vl;
#pragma unroll
    for (int qi = 0; qi < 4; qi++) {
        float e = valid ? __expf(sc[qi]) : 0.f;
        srow[(size_t)(q0 + qi) * Kn] = e;
        float t = e;
#pragma unroll
        for (int o = 16; o; o >>= 1) t += __shfl_xor_sync(0xffffffffu, t, o);
        if (kk == 0) atomicAdd(&g_rowsum[b * Qn + qh + q0 + qi], t);
    }
}

// ---------------------------------------------------------------------------
// Zero d_out (poisoned before timing; av accumulates atomically) and
// g_rowsum (accumulated atomically every call — graph replay safe).
// ---------------------------------------------------------------------------
__global__ void zero_out_kernel(float* __restrict__ out) {
    const int idx = blockIdx.x * 256 + threadIdx.x;  // 65536 float4
    ((float4*)out)[idx] = make_float4(0.f, 0.f, 0.f, 0.f);
    if (idx < Bn * Qn / 4) {
        ((float4*)g_rowsum)[idx] = make_float4(0.f, 0.f, 0.f, 0.f);
    }
}

// ---------------------------------------------------------------------------
// AV as HMMA GEMM with fused normalization: attn = escore * (1/rowsum).
// Grid (16 k-chunks of 64, Bn); chunks beyond vlen exit.
// Epilogue: atomicAdd into pre-zeroed out. V staged natural [k][n] +
// ldmatrix + prefetch. 8 warps 2(M) x 4(N); warp tile 32q x 64n.
// ---------------------------------------------------------------------------
__global__ void __launch_bounds__(256, 1) av_mma_kernel(
    const float* __restrict__ V, const int* __restrict__ vlen,
    float* __restrict__ out) {
    const int b  = blockIdx.y;
    const int ck = blockIdx.x;
    const int k0 = ck * 64;
    if (k0 >= vlen[b]) return;  // uniform per CTA

    __shared__ __align__(16) __nv_bfloat16 sAh[64][APAD];  // attn [q][k]
    __shared__ __align__(16) __nv_bfloat16 sAl[64][APAD];
    __shared__ __align__(16) __nv_bfloat16 sVh[32][VPAD];  // V [k][n] natural
    __shared__ __align__(16) __nv_bfloat16 sVl[32][VPAD];
    __shared__ float sIS[64];                              // per-q 1/rowsum

    const int tid  = threadIdx.x;
    const int wid  = tid >> 5;
    const int lane = tid & 31;
    const int gid  = lane >> 2;
    const int tig  = lane & 3;
    const int lrow = lane & 15;
    const int lcol = (lane >> 4) * 8;
    const int wm   = (wid & 1) * 32;   // 2 x 32 = 64 q
    const int wn   = (wid >> 1) * 64;  // 4 x 64 = 256 dv

    if (tid < 64) sIS[tid] = 1.0f / g_rowsum[b * Qn + tid];

    float acc[2][8][4];
#pragma unroll
    for (int im = 0; im < 2; im++)
#pragma unroll
        for (int j = 0; j < 8; j++)
#pragma unroll
            for (int r = 0; r < 4; r++) acc[im][j][r] = 0.f;

    const float* Ab = g_escores + ((size_t)b * Qn) * Kn + k0;
    const float* Vb = V + ((size_t)b * Kn + k0) * DVn;

    float4 aPre[2], vPre[8];
#pragma unroll
    for (int i = 0; i < 2; i++) {
        int idx = tid + i * 256;
        int r = idx >> 3, kq = idx & 7;
        aPre[i] = *(const float4*)&Ab[(size_t)r * Kn + kq * 4];
    }
#pragma unroll
    for (int i = 0; i < 8; i++) {
        int idx = tid + i * 256;
        int k = idx >> 6, n4 = idx & 63;
        vPre[i] = *(const float4*)&Vb[(size_t)k * DVn + n4 * 4];
    }
    __syncthreads();  // sIS visible before first staging conversion

    for (int kc = 0; kc < 64; kc += KC) {
#pragma unroll
        for (int i = 0; i < 2; i++) {
            int idx = tid + i * 256;
            int r = idx >> 3, kq = idx & 7;
            float4 v = aPre[i];
            float is = sIS[r];
            float px = v.x * is, py = v.y * is;
            float pz = v.z * is, pw = v.w * is;
            *(__nv_bfloat162*)&sAh[r][kq * 4]     = hi2(px, py);
            *(__nv_bfloat162*)&sAh[r][kq * 4 + 2] = hi2(pz, pw);
            *(__nv_bfloat162*)&sAl[r][kq * 4]     = lo2(px, py);
            *(__nv_bfloat162*)&sAl[r][kq * 4 + 2] = lo2(pz, pw);
        }
#pragma unroll
        for (int i = 0; i < 8; i++) {
            int idx = tid + i * 256;
            int k = idx >> 6, n4 = idx & 63;
            float4 v = vPre[i];
            *(__nv_bfloat162*)&sVh[k][n4 * 4]     = hi2(v.x, v.y);
            *(__nv_bfloat162*)&sVh[k][n4 * 4 + 2] = hi2(v.z, v.w);
            *(__nv_bfloat162*)&sVl[k][n4 * 4]     = lo2(v.x, v.y);
            *(__nv_bfloat162*)&sVl[k][n4 * 4 + 2] = lo2(v.z, v.w);
        }
        __syncthreads();

        if (kc + KC < 64) {
#pragma unroll
            for (int i = 0; i < 2; i++) {
                int idx = tid + i * 256;
                int r = idx >> 3, kq = idx & 7;
                aPre[i] = *(const float4*)
                    &Ab[(size_t)r * Kn + kc + KC + kq * 4];
            }
#pragma unroll
            for (int i = 0; i < 8; i++) {
                int idx = tid + i * 256;
                int k = idx >> 6, n4 = idx & 63;
                vPre[i] = *(const float4*)
                    &Vb[(size_t)(kc + KC + k) * DVn + n4 * 4];
            }
        }

#pragma unroll
        for (int s = 0; s < 2; s++) {
            uint32_t Ah2[2][4], Al2[2][4];
#pragma unroll
            for (int im = 0; im < 2; im++) {
                ldm_x4(Ah2[im], &sAh[wm + im * 16 + lrow][s * 16 + lcol]);
                ldm_x4(Al2[im], &sAl[wm + im * 16 + lrow][s * 16 + lcol]);
            }
            uint32_t Bh[8][2], Bl[8][2];
#pragma unroll
            for (int jj = 0; jj < 4; jj++) {
                uint32_t t[4];
                ldm_x4t(t, &sVh[s * 16 + lrow][wn + jj * 16 + lcol]);
                Bh[jj * 2][0] = t[0]; Bh[jj * 2][1] = t[1];
                Bh[jj * 2 + 1][0] = t[2]; Bh[jj * 2 + 1][1] = t[3];
                ldm_x4t(t, &sVl[s * 16 + lrow][wn + jj * 16 + lcol]);
                Bl[jj * 2][0] = t[0]; Bl[jj * 2][1] = t[1];
                Bl[jj * 2 + 1][0] = t[2]; Bl[jj * 2 + 1][1] = t[3];
            }
#pragma unroll
            for (int im = 0; im < 2; im++) {
#pragma unroll
                for (int j = 0; j < 8; j++) {
                    mma16816(acc[im][j], Ah2[im], Bh[j]);
                    mma16816(acc[im][j], Al2[im], Bh[j]);
                    mma16816(acc[im][j], Ah2[im], Bl[j]);
                }
            }
        }
        __syncthreads();
    }

    float* Ob = out + ((size_t)b * Qn) * DVn;
#pragma unroll
    for (int im = 0; im < 2; im++) {
        int r = wm + im * 16 + gid;
#pragma unroll
        for (int j = 0; j < 8; j++) {
            int c = wn + j * 8 + tig * 2;
            atomicAdd(&Ob[(size_t)r * DVn + c],           acc[im][j][0]);
            atomicAdd(&Ob[(size_t)r * DVn + c + 1],       acc[im][j][1]);
            atomicAdd(&Ob[(size_t)(r + 8) * DVn + c],     acc[im][j][2]);
            atomicAdd(&Ob[(size_t)(r + 8) * DVn + c + 1], acc[im][j][3]);
        }
    }
}

// ---------------------------------------------------------------------------
extern "C" void kernel_launch(void* const* d_in, const int* in_sizes, int n_in,
                              void* d_out, int out_size) {
    const float* queries = (const float*)d_in[0];
    const float* keys    = (const float*)d_in[1];
    const float* values  = (const float*)d_in[2];
    const int*   vlens   = (const int*)d_in[3];
    const float* Wq      = (const float*)d_in[4];
    const float* Wk      = (const float*)d_in[5];
    const float* wv      = (const float*)d_in[6];
    float* out           = (float*)d_out;

    zero_out_kernel<<<Bn * Qn * DVn / 1024, 256>>>(out);
    proj_mma_kernel<<<136, 256>>>(keys, queries, Wk, Wq, vlens);
    scores_kernel<<<dim3(Kn / 32, 2, Bn), 256>>>(wv, vlens);
    av_mma_kernel<<<dim3(16, Bn), 256>>>(values, vlens, out);
}